// round 9
// baseline (speedup 1.0000x reference)
#include <cuda_runtime.h>

#define NT 256

__device__ __forceinline__ float relu(float x) { return fmaxf(x, 0.0f); }

__constant__ int c_P0[8] = {0, 0, 4, 1, 2, 2, 6, 3};
__constant__ int c_P1[8] = {4, 1, 5, 5, 6, 3, 7, 7};

struct __align__(16) SW {
    float dv_w1[16], dv_b1[16], dv_w2[64], dv_b2[32];
    float dp_w1[16], dp_b1[16], dp_w2[64], dp_b2[32];
    float emb_w[128], emb_b[16];
    float cp_w1[640], cp_b1[20], cp_w2[400], cp_b2[20];
    float cm_w1[4],  cm_b1[4],  cm_w2[80],  cm_b2[20], cm_w3[400], cm_b3[20];
    float cc_w1[160], cc_b1[8], cc_w2[8],  cc_b2[4];
    float q_w1[128], q_b1[16], q_w2[256], q_b2[16], q_w3[128], q_b3[8];
    float mask[56], st[16];
};

__device__ __forceinline__ void cp16(float* s, const float* g) {
    unsigned sa = (unsigned)__cvta_generic_to_shared(s);
    asm volatile("cp.async.cg.shared.global [%0], [%1], 16;" :: "r"(sa), "l"(g));
}
__device__ __forceinline__ void cp4(float* s, const float* g) {
    unsigned sa = (unsigned)__cvta_generic_to_shared(s);
    asm volatile("cp.async.ca.shared.global [%0], [%1], 4;" :: "r"(sa), "l"(g));
}
// per-warp copy: n multiple of 4
__device__ __forceinline__ void cpw(float* dst, const float* src, int n, int lane) {
    for (int i = lane; i < (n >> 2); i += 32) cp16(dst + i * 4, src + i * 4);
}

__device__ __forceinline__ float dot4(const float4 wv, const float* a) {
    return wv.x * a[0] + wv.y * a[1] + wv.z * a[2] + wv.w * a[3];
}

__global__ void __launch_bounds__(NT, 1)
frap_fused_kernel(
    const float* __restrict__ state, int B,
    const float* __restrict__ dv_w1, const float* __restrict__ dv_b1,
    const float* __restrict__ dv_w2, const float* __restrict__ dv_b2,
    const float* __restrict__ dp_w1, const float* __restrict__ dp_b1,
    const float* __restrict__ dp_w2, const float* __restrict__ dp_b2,
    const float* __restrict__ emb_w, const float* __restrict__ emb_b,
    const float* __restrict__ cp_w1, const float* __restrict__ cp_b1,
    const float* __restrict__ cp_w2, const float* __restrict__ cp_b2,
    const float* __restrict__ cm_w1, const float* __restrict__ cm_b1,
    const float* __restrict__ cm_w2, const float* __restrict__ cm_b2,
    const float* __restrict__ cm_w3, const float* __restrict__ cm_b3,
    const float* __restrict__ cc_w1, const float* __restrict__ cc_b1,
    const float* __restrict__ cc_w2, const float* __restrict__ cc_b2,
    const float* __restrict__ q_w1,  const float* __restrict__ q_b1,
    const float* __restrict__ q_w2,  const float* __restrict__ q_b2,
    const float* __restrict__ q_w3,  const float* __restrict__ q_b3,
    const float* __restrict__ mask,
    float4* __restrict__ out, int n4)
{
    __shared__ SW w;
    __shared__ float s_cat[8][8];
    __shared__ float s_d[8][16];
    __shared__ float s_z[32][56];
    __shared__ float s_z0[20][56];
    __shared__ float s_z1[20][56];
    __shared__ float s_z1c[20];
    __shared__ __align__(16) float s_y1tab[2][20];
    __shared__ __align__(16) float s_y2tab[2][20];
    __shared__ float s_rc1l[8][56];
    __shared__ float s_rc1c[2][8];
    __shared__ float s_rc2l[56];
    __shared__ float s_rc2c[2];
    __shared__ float s_rsum[2][8];
    __shared__ float s_h1[2][16];
    __shared__ float s_h2[2][16];
    __shared__ __align__(16) float s_q[2][8];  // [0]=last row, [1]=common

    const int t = threadIdx.x;
    const int warp = t >> 5, lane = t & 31;
    const bool heavy = (blockIdx.x == 0);

    // ---- Per-warp self-sufficient prefetch: each warp copies what IT needs
    //      pre-barrier, waits only its own group, computes its stage-A piece. ----
    switch (warp) {
    case 0:  // cat -> d (heavy only) ; also q_w3 (post-barrier use)
        if (heavy) {
            cpw(w.dv_w1, dv_w1, 16, lane);  cpw(w.dv_b1, dv_b1, 16, lane);
            cpw(w.dv_w2, dv_w2, 64, lane);  cpw(w.dv_b2, dv_b2, 32, lane);
            cpw(w.dp_w1, dp_w1, 16, lane);  cpw(w.dp_b1, dp_b1, 16, lane);
            cpw(w.dp_w2, dp_w2, 64, lane);  cpw(w.dp_b2, dp_b2, 32, lane);
            cpw(w.emb_w, emb_w, 128, lane); cpw(w.emb_b, emb_b, 16, lane);
            cpw(w.st, state + (size_t)(B - 1) * 16, 16, lane);
        }
        cpw(w.q_w3, q_w3, 128, lane); cpw(w.q_b3, q_b3, 8, lane);
        break;
    case 1:  // z1c
        cpw(w.cp_w2, cp_w2, 400, lane);
        cpw(w.cp_b1, cp_b1, 20, lane); cpw(w.cp_b2, cp_b2, 20, lane);
        break;
    case 2:  // y1tab -> y2tab
        cpw(w.cm_w3, cm_w3, 400, lane); cpw(w.cm_w2, cm_w2, 80, lane);
        cpw(w.cm_b2, cm_b2, 20, lane);  cpw(w.cm_b3, cm_b3, 20, lane);
        cpw(w.cm_w1, cm_w1, 4, lane);   cpw(w.cm_b1, cm_b1, 4, lane);
        break;
    case 3: if (heavy) cpw(w.cp_w1, cp_w1, 320, lane); break;
    case 6: if (heavy) cpw(w.cp_w1 + 320, cp_w1 + 320, 320, lane); break;
    case 4:
        cpw(w.cc_w1, cc_w1, 160, lane); cpw(w.cc_b1, cc_b1, 8, lane);
        cpw(w.cc_w2, cc_w2, 8, lane);   cpw(w.mask, mask, 56, lane);
        if (lane == 0) cp4(w.cc_b2, cc_b2);
        break;
    case 5:
        cpw(w.q_w1, q_w1, 128, lane); cpw(w.q_b1, q_b1, 16, lane);
        cpw(w.q_b2, q_b2, 16, lane);
        break;
    case 7:
        cpw(w.q_w2, q_w2, 256, lane);
        break;
    }
    asm volatile("cp.async.commit_group;");
    asm volatile("cp.async.wait_group 0;");

    // ---- Stage A (warp-local, pre-barrier): warp0 cat->d | warp1 z1c | warp2 tabs ----
    if (warp == 0 && heavy) {
        if (lane < 8) {
            const int p = lane;
            const float sv = w.st[p];
            const float sp = w.st[8 + p];
            float h0 = relu(sv * w.dv_w1[p * 2 + 0] + w.dv_b1[p * 2 + 0]);
            float h1 = relu(sv * w.dv_w1[p * 2 + 1] + w.dv_b1[p * 2 + 1]);
            #pragma unroll
            for (int o = 0; o < 4; o++)
                s_cat[p][o] = relu(h0 * w.dv_w2[p * 8 + o * 2 + 0] +
                                   h1 * w.dv_w2[p * 8 + o * 2 + 1] + w.dv_b2[p * 4 + o]);
            h0 = relu(sp * w.dp_w1[p * 2 + 0] + w.dp_b1[p * 2 + 0]);
            h1 = relu(sp * w.dp_w1[p * 2 + 1] + w.dp_b1[p * 2 + 1]);
            #pragma unroll
            for (int o = 0; o < 4; o++)
                s_cat[p][4 + o] = relu(h0 * w.dp_w2[p * 8 + o * 2 + 0] +
                                       h1 * w.dp_w2[p * 8 + o * 2 + 1] + w.dp_b2[p * 4 + o]);
        }
        __syncwarp();
        #pragma unroll
        for (int u = 0; u < 4; u++) {
            const int o128 = lane + u * 32;
            const int p = o128 >> 4, k = o128 & 15;
            const float4* w4 = reinterpret_cast<const float4*>(&w.emb_w[k * 8]);
            s_d[p][k] = relu(w.emb_b[k] + dot4(w4[0], &s_cat[p][0]) + dot4(w4[1], &s_cat[p][4]));
        }
    } else if (warp == 1) {
        if (lane < 20) {
            const int o = lane;
            float acc = w.cp_b2[o];
            const float4* w4 = reinterpret_cast<const float4*>(&w.cp_w2[o * 20]);
            #pragma unroll
            for (int c4 = 0; c4 < 5; c4++) {
                const float4 wv = w4[c4];
                acc += wv.x * relu(w.cp_b1[c4 * 4 + 0]) + wv.y * relu(w.cp_b1[c4 * 4 + 1])
                     + wv.z * relu(w.cp_b1[c4 * 4 + 2]) + wv.w * relu(w.cp_b1[c4 * 4 + 3]);
            }
            s_z1c[o] = relu(acc);
        }
    } else if (warp == 2) {
        if (lane < 20) {
            #pragma unroll
            for (int mi = 0; mi < 2; mi++) {
                const float m = mi ? 1.0f : 0.5f;
                float hid[4];
                #pragma unroll
                for (int c = 0; c < 4; c++) hid[c] = relu(w.cm_w1[c] * m + w.cm_b1[c]);
                const float4 wv = *reinterpret_cast<const float4*>(&w.cm_w2[lane * 4]);
                s_y1tab[mi][lane] = relu(w.cm_b2[lane] + dot4(wv, hid));
            }
        }
        __syncwarp();
        if (lane < 20) {
            const float4* w4 = reinterpret_cast<const float4*>(&w.cm_w3[lane * 20]);
            #pragma unroll
            for (int mi = 0; mi < 2; mi++) {
                float acc = w.cm_b3[lane];
                #pragma unroll
                for (int c4 = 0; c4 < 5; c4++) acc += dot4(w4[c4], &s_y1tab[mi][c4 * 4]);
                s_y2tab[mi][lane] = relu(acc);
            }
        }
    }
    __syncthreads();   // barrier 1: s_d, z1c, y2tab, all weights visible

    // ==== Warp-autonomous pipelines ====
    if (warp == 7) {
        // Common chain: rc1c -> rc2c -> rsumc -> q_common (all blocks)
        if (lane < 16) {
            const int mi = lane >> 3, o = lane & 7;
            const float4* w4 = reinterpret_cast<const float4*>(&w.cc_w1[o * 20]);
            float rv[20];
            #pragma unroll
            for (int c = 0; c < 20; c++) rv[c] = s_z1c[c] * s_y2tab[mi][c];
            float acc = w.cc_b1[o];
            #pragma unroll
            for (int c4 = 0; c4 < 5; c4++) acc += dot4(w4[c4], &rv[c4 * 4]);
            s_rc1c[mi][o] = relu(acc);
        }
        __syncwarp();
        if (lane < 2) {
            float acc = w.cc_b2[0];
            #pragma unroll
            for (int c = 0; c < 8; c++) acc += w.cc_w2[c] * s_rc1c[lane][c];
            s_rc2c[lane] = relu(acc);
        }
        __syncwarp();
        if (lane < 8) {
            float acc = 0.0f;
            #pragma unroll
            for (int h = 0; h < 7; h++) {
                const int bit = (w.mask[h * 8 + lane] == 1.0f) ? 1 : 0;
                acc += s_rc2c[bit];
            }
            s_rsum[1][lane] = acc;
        }
        __syncwarp();
        if (lane < 16) {
            const float4* w4 = reinterpret_cast<const float4*>(&w.q_w1[lane * 8]);
            s_h1[1][lane] = relu(w.q_b1[lane] + dot4(w4[0], &s_rsum[1][0]) + dot4(w4[1], &s_rsum[1][4]));
        }
        __syncwarp();
        if (lane < 16) {
            const float4* w4 = reinterpret_cast<const float4*>(&w.q_w2[lane * 16]);
            float acc = w.q_b2[lane];
            #pragma unroll
            for (int c4 = 0; c4 < 4; c4++) acc += dot4(w4[c4], &s_h1[1][c4 * 4]);
            s_h2[1][lane] = relu(acc);
        }
        __syncwarp();
        if (lane < 8) {
            const float4* w4 = reinterpret_cast<const float4*>(&w.q_w3[lane * 16]);
            float acc = w.q_b3[lane];
            #pragma unroll
            for (int c4 = 0; c4 < 4; c4++) acc += dot4(w4[c4], &s_h2[1][c4 * 4]);
            s_q[1][lane] = relu(acc);
        }
    } else if (heavy) {
        // Warps 0-6: own 8 positions end-to-end; only __syncwarp between sub-stages.
        const int pos = (warp << 3) | (lane >> 2);   // 8 pos per warp, 56 total
        const int og = lane & 3;

        // z: channels og*8 .. og*8+7 for this pos
        #pragma unroll
        for (int u = 0; u < 8; u++) {
            const int c = og * 8 + u;
            const int idx = c * 56 + pos;
            const int r = idx >> 8, col = (idx >> 5) & 7, k = idx & 31;
            const int i = (r < col) ? r : r + 1;
            const int sel = (k < 16) ? i : col;
            const int kk = k & 15;
            s_z[c][pos] = s_d[c_P0[sel]][kk] + s_d[c_P1[sel]][kk];
        }
        __syncwarp();

        // z0: outputs og*5 .. og*5+4
        {
            float act[32];
            #pragma unroll
            for (int c = 0; c < 32; c++) act[c] = s_z[c][pos];
            #pragma unroll
            for (int u = 0; u < 5; u++) {
                const int o = og * 5 + u;
                const float4* w4 = reinterpret_cast<const float4*>(&w.cp_w1[o * 32]);
                float acc = w.cp_b1[o];
                #pragma unroll
                for (int c4 = 0; c4 < 8; c4++) acc += dot4(w4[c4], &act[c4 * 4]);
                s_z0[o][pos] = relu(acc);
            }
        }
        __syncwarp();

        // z1
        {
            float act[20];
            #pragma unroll
            for (int c = 0; c < 20; c++) act[c] = s_z0[c][pos];
            #pragma unroll
            for (int u = 0; u < 5; u++) {
                const int o = og * 5 + u;
                const float4* w4 = reinterpret_cast<const float4*>(&w.cp_w2[o * 20]);
                float acc = w.cp_b2[o];
                #pragma unroll
                for (int c4 = 0; c4 < 5; c4++) acc += dot4(w4[c4], &act[c4 * 4]);
                s_z1[o][pos] = relu(acc);
            }
        }
        __syncwarp();

        // rc1: outputs og*2, og*2+1
        {
            const int bit = (w.mask[pos] == 1.0f) ? 1 : 0;
            float rv[20];
            #pragma unroll
            for (int c = 0; c < 20; c++) rv[c] = s_z1[c][pos] * s_y2tab[bit][c];
            #pragma unroll
            for (int u = 0; u < 2; u++) {
                const int o = og * 2 + u;
                const float4* w4 = reinterpret_cast<const float4*>(&w.cc_w1[o * 20]);
                float acc = w.cc_b1[o];
                #pragma unroll
                for (int c4 = 0; c4 < 5; c4++) acc += dot4(w4[c4], &rv[c4 * 4]);
                s_rc1l[o][pos] = relu(acc);
            }
        }
        __syncwarp();

        // rc2: one lane per pos (og == 0)
        if (og == 0) {
            float acc = w.cc_b2[0];
            #pragma unroll
            for (int c = 0; c < 8; c++) acc += w.cc_w2[c] * s_rc1l[c][pos];
            s_rc2l[pos] = relu(acc);
        }
    }
    __syncthreads();   // barrier 2: rc2l (heavy) + q_common visible

    if (heavy) {
        // Warp 0: last-path tail rsum -> Q-net -> write last row
        if (warp == 0) {
            if (lane < 8) {
                float acc = 0.0f;
                #pragma unroll
                for (int h = 0; h < 7; h++) acc += s_rc2l[h * 8 + lane];
                s_rsum[0][lane] = acc;
            }
            __syncwarp();
            if (lane < 16) {
                const float4* w4 = reinterpret_cast<const float4*>(&w.q_w1[lane * 8]);
                s_h1[0][lane] = relu(w.q_b1[lane] + dot4(w4[0], &s_rsum[0][0]) + dot4(w4[1], &s_rsum[0][4]));
            }
            __syncwarp();
            if (lane < 16) {
                const float4* w4 = reinterpret_cast<const float4*>(&w.q_w2[lane * 16]);
                float acc = w.q_b2[lane];
                #pragma unroll
                for (int c4 = 0; c4 < 4; c4++) acc += dot4(w4[c4], &s_h1[0][c4 * 4]);
                s_h2[0][lane] = relu(acc);
            }
            __syncwarp();
            if (lane < 8) {
                const float4* w4 = reinterpret_cast<const float4*>(&w.q_w3[lane * 16]);
                float acc = w.q_b3[lane];
                #pragma unroll
                for (int c4 = 0; c4 < 4; c4++) acc += dot4(w4[c4], &s_h2[0][c4 * 4]);
                s_q[0][lane] = relu(acc);
            }
            __syncwarp();
            if (lane < 2) {
                out[n4 - 2 + lane] = (lane == 0)
                    ? *reinterpret_cast<const float4*>(&s_q[0][0])
                    : *reinterpret_cast<const float4*>(&s_q[0][4]);
            }
        }
    } else {
        // Light blocks: fill rows 0..B-2 with q_common
        const float4 qc0 = *reinterpret_cast<const float4*>(&s_q[1][0]);
        const float4 qc1 = *reinterpret_cast<const float4*>(&s_q[1][4]);
        const int stride = (gridDim.x - 1) * NT;
        for (int i = (blockIdx.x - 1) * NT + t; i < n4 - 2; i += stride)
            out[i] = (i & 1) ? qc1 : qc0;
    }
}

extern "C" void kernel_launch(void* const* d_in, const int* in_sizes, int n_in,
                              void* d_out, int out_size) {
    const float* state = (const float*)d_in[0];
    const int B = in_sizes[0] / 16;

    const float* dv_w1 = (const float*)d_in[1];
    const float* dv_b1 = (const float*)d_in[2];
    const float* dv_w2 = (const float*)d_in[3];
    const float* dv_b2 = (const float*)d_in[4];
    const float* dp_w1 = (const float*)d_in[5];
    const float* dp_b1 = (const float*)d_in[6];
    const float* dp_w2 = (const float*)d_in[7];
    const float* dp_b2 = (const float*)d_in[8];
    const float* emb_w = (const float*)d_in[9];
    const float* emb_b = (const float*)d_in[10];
    const float* cp_w1 = (const float*)d_in[11];
    const float* cp_b1 = (const float*)d_in[12];
    const float* cp_w2 = (const float*)d_in[13];
    const float* cp_b2 = (const float*)d_in[14];
    const float* cm_w1 = (const float*)d_in[15];
    const float* cm_b1 = (const float*)d_in[16];
    const float* cm_w2 = (const float*)d_in[17];
    const float* cm_b2 = (const float*)d_in[18];
    const float* cm_w3 = (const float*)d_in[19];
    const float* cm_b3 = (const float*)d_in[20];
    const float* cc_w1 = (const float*)d_in[21];
    const float* cc_b1 = (const float*)d_in[22];
    const float* cc_w2 = (const float*)d_in[23];
    const float* cc_b2 = (const float*)d_in[24];
    const float* q_w1  = (const float*)d_in[25];
    const float* q_b1  = (const float*)d_in[26];
    const float* q_w2  = (const float*)d_in[27];
    const float* q_b2  = (const float*)d_in[28];
    const float* q_w3  = (const float*)d_in[29];
    const float* q_b3  = (const float*)d_in[30];
    const float* mask  = (const float*)d_in[31];

    const int n4 = out_size / 4;
    frap_fused_kernel<<<148, NT>>>(
        state, B,
        dv_w1, dv_b1, dv_w2, dv_b2,
        dp_w1, dp_b1, dp_w2, dp_b2,
        emb_w, emb_b,
        cp_w1, cp_b1, cp_w2, cp_b2,
        cm_w1, cm_b1, cm_w2, cm_b2, cm_w3, cm_b3,
        cc_w1, cc_b1, cc_w2, cc_b2,
        q_w1, q_b1, q_w2, q_b2, q_w3, q_b3,
        mask,
        (float4*)d_out, n4);
}

// round 11
// speedup vs baseline: 1.3092x; 1.3092x over previous
#include <cuda_runtime.h>

#define NT 256

__device__ __forceinline__ float relu(float x) { return fmaxf(x, 0.0f); }

__constant__ int c_P0[8] = {0, 0, 4, 1, 2, 2, 6, 3};
__constant__ int c_P1[8] = {4, 1, 5, 5, 6, 3, 7, 7};

struct __align__(16) SW {
    float dv_w1[16], dv_b1[16], dv_w2[64], dv_b2[32];
    float dp_w1[16], dp_b1[16], dp_w2[64], dp_b2[32];
    float emb_w[128], emb_b[16];
    float cp_w1[640], cp_b1[20], cp_w2[400], cp_b2[20];
    float cm_w1[4],  cm_b1[4],  cm_w2[80],  cm_b2[20], cm_w3[400], cm_b3[20];
    float cc_w1[160], cc_b1[8], cc_w2[8],  cc_b2[4];
    float q_w1[128], q_b1[16], q_w2[256], q_b2[16], q_w3[128], q_b3[8];
    float mask[56], st[16];
};

__device__ __forceinline__ void cp16(float* s, const float* g) {
    unsigned sa = (unsigned)__cvta_generic_to_shared(s);
    asm volatile("cp.async.cg.shared.global [%0], [%1], 16;" :: "r"(sa), "l"(g));
}
__device__ __forceinline__ void cp4(float* s, const float* g) {
    unsigned sa = (unsigned)__cvta_generic_to_shared(s);
    asm volatile("cp.async.ca.shared.global [%0], [%1], 4;" :: "r"(sa), "l"(g));
}
// per-warp copy: n multiple of 4
__device__ __forceinline__ void cpw(float* dst, const float* src, int n, int lane) {
    for (int i = lane; i < (n >> 2); i += 32) cp16(dst + i * 4, src + i * 4);
}

__device__ __forceinline__ float dot4(const float4 wv, const float* a) {
    return wv.x * a[0] + wv.y * a[1] + wv.z * a[2] + wv.w * a[3];
}

__global__ void __launch_bounds__(NT, 1)
frap_fused_kernel(
    const float* __restrict__ state, int B,
    const float* __restrict__ dv_w1, const float* __restrict__ dv_b1,
    const float* __restrict__ dv_w2, const float* __restrict__ dv_b2,
    const float* __restrict__ dp_w1, const float* __restrict__ dp_b1,
    const float* __restrict__ dp_w2, const float* __restrict__ dp_b2,
    const float* __restrict__ emb_w, const float* __restrict__ emb_b,
    const float* __restrict__ cp_w1, const float* __restrict__ cp_b1,
    const float* __restrict__ cp_w2, const float* __restrict__ cp_b2,
    const float* __restrict__ cm_w1, const float* __restrict__ cm_b1,
    const float* __restrict__ cm_w2, const float* __restrict__ cm_b2,
    const float* __restrict__ cm_w3, const float* __restrict__ cm_b3,
    const float* __restrict__ cc_w1, const float* __restrict__ cc_b1,
    const float* __restrict__ cc_w2, const float* __restrict__ cc_b2,
    const float* __restrict__ q_w1,  const float* __restrict__ q_b1,
    const float* __restrict__ q_w2,  const float* __restrict__ q_b2,
    const float* __restrict__ q_w3,  const float* __restrict__ q_b3,
    const float* __restrict__ mask,
    float4* __restrict__ out, int n4)
{
    __shared__ SW w;
    __shared__ float s_cat[8][8];
    __shared__ float s_d[8][16];
    __shared__ float s_z[32][56];
    __shared__ float s_z0[20][56];
    __shared__ float s_z1[20][56];
    __shared__ float s_z1c[20];
    __shared__ __align__(16) float s_y1tab[2][20];
    __shared__ __align__(16) float s_y2tab[2][20];
    __shared__ float s_rc1l[8][56];
    __shared__ float s_rc1c[2][8];
    __shared__ float s_rc2l[56];
    __shared__ float s_rc2c[2];
    __shared__ float s_rsum[2][8];
    __shared__ float s_h1[2][16];
    __shared__ float s_h2[2][16];
    __shared__ __align__(16) float s_q[2][8];  // [0]=last row, [1]=common

    const int t = threadIdx.x;
    const int warp = t >> 5, lane = t & 31;
    const bool heavy = (blockIdx.x == 0);

    // ---- Phase-0 prefetch (stage A-C data), balanced <= ~50 cp16/warp ----
    switch (warp) {
    case 0: cpw(w.cm_w3, cm_w3, 200, lane); break;
    case 1: cpw(w.cm_w3 + 200, cm_w3 + 200, 200, lane); break;
    case 2: cpw(w.cp_w2, cp_w2, 200, lane); break;
    case 3: cpw(w.cp_w2 + 200, cp_w2 + 200, 200, lane); break;
    case 4: cpw(w.cm_w2, cm_w2, 80, lane);  cpw(w.cm_b2, cm_b2, 20, lane);
            cpw(w.cm_b3, cm_b3, 20, lane);  cpw(w.cm_w1, cm_w1, 4, lane);
            cpw(w.cm_b1, cm_b1, 4, lane);   break;
    case 5: cpw(w.cp_b1, cp_b1, 20, lane);  cpw(w.cp_b2, cp_b2, 20, lane);
            cpw(w.mask, mask, 56, lane);
            if (heavy) cpw(w.st, state + (size_t)(B - 1) * 16, 16, lane);
            break;
    case 6: if (heavy) {
                cpw(w.dv_w1, dv_w1, 16, lane);  cpw(w.dv_b1, dv_b1, 16, lane);
                cpw(w.dv_w2, dv_w2, 64, lane);  cpw(w.dv_b2, dv_b2, 32, lane);
                cpw(w.dp_w1, dp_w1, 16, lane);  cpw(w.dp_b1, dp_b1, 16, lane);
                cpw(w.dp_w2, dp_w2, 64, lane);  cpw(w.dp_b2, dp_b2, 32, lane);
            }
            break;
    case 7: if (heavy) { cpw(w.emb_w, emb_w, 128, lane); cpw(w.emb_b, emb_b, 16, lane); }
            break;
    }
    asm volatile("cp.async.commit_group;");
    // ---- Phase-1 prefetch (stage D+ data), balanced, waited at stage D ----
    switch (warp) {
    case 0: if (heavy) cpw(w.cp_w1, cp_w1, 160, lane); break;
    case 1: if (heavy) cpw(w.cp_w1 + 160, cp_w1 + 160, 160, lane); break;
    case 2: if (heavy) cpw(w.cp_w1 + 320, cp_w1 + 320, 160, lane); break;
    case 3: if (heavy) cpw(w.cp_w1 + 480, cp_w1 + 480, 160, lane); break;
    case 4: cpw(w.q_w2, q_w2, 256, lane); break;
    case 5: cpw(w.q_w1, q_w1, 128, lane); cpw(w.q_b1, q_b1, 16, lane);
            cpw(w.q_b2, q_b2, 16, lane);  break;
    case 6: cpw(w.q_w3, q_w3, 128, lane); cpw(w.q_b3, q_b3, 8, lane); break;
    case 7: cpw(w.cc_w1, cc_w1, 160, lane); cpw(w.cc_b1, cc_b1, 8, lane);
            cpw(w.cc_w2, cc_w2, 8, lane);
            if (lane == 0) cp4(w.cc_b2, cc_b2);
            break;
    }
    asm volatile("cp.async.commit_group;");
    asm volatile("cp.async.wait_group 1;");   // phase-0 landed
    __syncthreads();

    // ==== Stage A: warp0 cat->d (heavy; dv/dp halves in parallel) | warp1 z1c | warp2/3 y1tab ====
    if (warp == 0 && heavy) {
        if (lane < 16) {
            const int p = lane & 7;
            if (lane < 8) {
                const float sv = w.st[p];
                float h0 = relu(sv * w.dv_w1[p * 2 + 0] + w.dv_b1[p * 2 + 0]);
                float h1 = relu(sv * w.dv_w1[p * 2 + 1] + w.dv_b1[p * 2 + 1]);
                #pragma unroll
                for (int o = 0; o < 4; o++)
                    s_cat[p][o] = relu(h0 * w.dv_w2[p * 8 + o * 2 + 0] +
                                       h1 * w.dv_w2[p * 8 + o * 2 + 1] + w.dv_b2[p * 4 + o]);
            } else {
                const float sp = w.st[8 + p];
                float h0 = relu(sp * w.dp_w1[p * 2 + 0] + w.dp_b1[p * 2 + 0]);
                float h1 = relu(sp * w.dp_w1[p * 2 + 1] + w.dp_b1[p * 2 + 1]);
                #pragma unroll
                for (int o = 0; o < 4; o++)
                    s_cat[p][4 + o] = relu(h0 * w.dp_w2[p * 8 + o * 2 + 0] +
                                           h1 * w.dp_w2[p * 8 + o * 2 + 1] + w.dp_b2[p * 4 + o]);
            }
        }
        __syncwarp();
        #pragma unroll
        for (int u = 0; u < 4; u++) {
            const int o128 = lane + u * 32;
            const int p = o128 >> 4, k = o128 & 15;
            const float4* w4 = reinterpret_cast<const float4*>(&w.emb_w[k * 8]);
            s_d[p][k] = relu(w.emb_b[k] + dot4(w4[0], &s_cat[p][0]) + dot4(w4[1], &s_cat[p][4]));
        }
    } else if (warp == 1) {
        if (lane < 20) {
            const int o = lane;
            float acc = w.cp_b2[o];
            const float4* w4 = reinterpret_cast<const float4*>(&w.cp_w2[o * 20]);
            #pragma unroll
            for (int c4 = 0; c4 < 5; c4++) {
                const float4 wv = w4[c4];
                acc += wv.x * relu(w.cp_b1[c4 * 4 + 0]) + wv.y * relu(w.cp_b1[c4 * 4 + 1])
                     + wv.z * relu(w.cp_b1[c4 * 4 + 2]) + wv.w * relu(w.cp_b1[c4 * 4 + 3]);
            }
            s_z1c[o] = relu(acc);
        }
    } else if (warp == 2 || warp == 3) {
        const int mi = warp - 2;
        const float m = mi ? 1.0f : 0.5f;
        if (lane < 20) {
            float hid[4];
            #pragma unroll
            for (int c = 0; c < 4; c++) hid[c] = relu(w.cm_w1[c] * m + w.cm_b1[c]);
            const float4 wv = *reinterpret_cast<const float4*>(&w.cm_w2[lane * 4]);
            s_y1tab[mi][lane] = relu(w.cm_b2[lane] + dot4(wv, hid));
        }
    }
    __syncthreads();

    // ==== Stage C: z build (heavy, t<224) | y2tab (all blocks, t in [192,232)) ====
    if (heavy && t < 224) {
        const int pos = t % 56, cg = t / 56;
        #pragma unroll
        for (int u = 0; u < 8; u++) {
            const int c = cg * 8 + u;
            const int idx = c * 56 + pos;
            const int r = idx >> 8, col = (idx >> 5) & 7, k = idx & 31;
            const int i = (r < col) ? r : r + 1;
            const int sel = (k < 16) ? i : col;
            const int kk = k & 15;
            s_z[c][pos] = s_d[c_P0[sel]][kk] + s_d[c_P1[sel]][kk];
        }
    }
    if (t >= 192 && t < 232) {
        const int mi = (t - 192) / 20, o = (t - 192) % 20;
        const float4* w4 = reinterpret_cast<const float4*>(&w.cm_w3[o * 20]);
        float acc = w.cm_b3[o];
        #pragma unroll
        for (int c4 = 0; c4 < 5; c4++) acc += dot4(w4[c4], &s_y1tab[mi][c4 * 4]);
        s_y2tab[mi][o] = relu(acc);
    }
    asm volatile("cp.async.wait_group 0;");   // phase-1 landed
    __syncthreads();

    // ==== Stage D: z0 (heavy, t<224) | warp7 (ALL blocks): full common chain ====
    if (warp == 7) {
        if (lane < 16) {
            const int mi = lane >> 3, o = lane & 7;
            const float4* w4 = reinterpret_cast<const float4*>(&w.cc_w1[o * 20]);
            float rv[20];
            #pragma unroll
            for (int c = 0; c < 20; c++) rv[c] = s_z1c[c] * s_y2tab[mi][c];
            float acc = w.cc_b1[o];
            #pragma unroll
            for (int c4 = 0; c4 < 5; c4++) acc += dot4(w4[c4], &rv[c4 * 4]);
            s_rc1c[mi][o] = relu(acc);
        }
        __syncwarp();
        if (lane < 2) {
            float acc = w.cc_b2[0];
            #pragma unroll
            for (int c = 0; c < 8; c++) acc += w.cc_w2[c] * s_rc1c[lane][c];
            s_rc2c[lane] = relu(acc);
        }
        __syncwarp();
        if (lane < 8) {
            float acc = 0.0f;
            #pragma unroll
            for (int h = 0; h < 7; h++) {
                const int bit = (w.mask[h * 8 + lane] == 1.0f) ? 1 : 0;
                acc += s_rc2c[bit];
            }
            s_rsum[1][lane] = acc;
        }
        __syncwarp();
        if (lane < 16) {
            const float4* w4 = reinterpret_cast<const float4*>(&w.q_w1[lane * 8]);
            s_h1[1][lane] = relu(w.q_b1[lane] + dot4(w4[0], &s_rsum[1][0]) + dot4(w4[1], &s_rsum[1][4]));
        }
        __syncwarp();
        if (lane < 16) {
            const float4* w4 = reinterpret_cast<const float4*>(&w.q_w2[lane * 16]);
            float acc = w.q_b2[lane];
            #pragma unroll
            for (int c4 = 0; c4 < 4; c4++) acc += dot4(w4[c4], &s_h1[1][c4 * 4]);
            s_h2[1][lane] = relu(acc);
        }
        __syncwarp();
        if (lane < 8) {
            const float4* w4 = reinterpret_cast<const float4*>(&w.q_w3[lane * 16]);
            float acc = w.q_b3[lane];
            #pragma unroll
            for (int c4 = 0; c4 < 4; c4++) acc += dot4(w4[c4], &s_h2[1][c4 * 4]);
            s_q[1][lane] = relu(acc);
        }
    } else if (heavy && t < 224) {
        const int pos = t % 56, og = t / 56;
        float act[32];
        #pragma unroll
        for (int c = 0; c < 32; c++) act[c] = s_z[c][pos];
        #pragma unroll
        for (int u = 0; u < 5; u++) {
            const int o = og * 5 + u;
            const float4* w4 = reinterpret_cast<const float4*>(&w.cp_w1[o * 32]);
            float acc = w.cp_b1[o];
            #pragma unroll
            for (int c4 = 0; c4 < 8; c4++) acc += dot4(w4[c4], &act[c4 * 4]);
            s_z0[o][pos] = relu(acc);
        }
    }
    __syncthreads();

    // ==== Stage E: z1 (heavy, t<224) ====
    if (heavy && t < 224) {
        const int pos = t % 56, og = t / 56;
        float act[20];
        #pragma unroll
        for (int c = 0; c < 20; c++) act[c] = s_z0[c][pos];
        #pragma unroll
        for (int u = 0; u < 5; u++) {
            const int o = og * 5 + u;
            const float4* w4 = reinterpret_cast<const float4*>(&w.cp_w2[o * 20]);
            float acc = w.cp_b2[o];
            #pragma unroll
            for (int c4 = 0; c4 < 5; c4++) acc += dot4(w4[c4], &act[c4 * 4]);
            s_z1[o][pos] = relu(acc);
        }
    }
    __syncthreads();

    // ==== Stage F: rc1 last path (heavy, t<224) ====
    if (heavy && t < 224) {
        const int pos = t % 56, og = t / 56;
        const int bit = (w.mask[pos] == 1.0f) ? 1 : 0;
        float rv[20];
        #pragma unroll
        for (int c = 0; c < 20; c++) rv[c] = s_z1[c][pos] * s_y2tab[bit][c];
        #pragma unroll
        for (int u = 0; u < 2; u++) {
            const int o = og * 2 + u;
            const float4* w4 = reinterpret_cast<const float4*>(&w.cc_w1[o * 20]);
            float acc = w.cc_b1[o];
            #pragma unroll
            for (int c4 = 0; c4 < 5; c4++) acc += dot4(w4[c4], &rv[c4 * 4]);
            s_rc1l[o][pos] = relu(acc);
        }
    }
    __syncthreads();

    // ==== Stage G: last-path tail (heavy, warp 0) ====
    if (heavy && warp == 0) {
        #pragma unroll
        for (int rep = 0; rep < 2; rep++) {
            const int pos = lane + rep * 32;
            if (pos < 56) {
                float acc = w.cc_b2[0];
                #pragma unroll
                for (int c = 0; c < 8; c++) acc += w.cc_w2[c] * s_rc1l[c][pos];
                s_rc2l[pos] = relu(acc);
            }
        }
        __syncwarp();
        if (lane < 8) {
            float acc = 0.0f;
            #pragma unroll
            for (int h = 0; h < 7; h++) acc += s_rc2l[h * 8 + lane];
            s_rsum[0][lane] = acc;
        }
        __syncwarp();
        if (lane < 16) {
            const float4* w4 = reinterpret_cast<const float4*>(&w.q_w1[lane * 8]);
            s_h1[0][lane] = relu(w.q_b1[lane] + dot4(w4[0], &s_rsum[0][0]) + dot4(w4[1], &s_rsum[0][4]));
        }
        __syncwarp();
        if (lane < 16) {
            const float4* w4 = reinterpret_cast<const float4*>(&w.q_w2[lane * 16]);
            float acc = w.q_b2[lane];
            #pragma unroll
            for (int c4 = 0; c4 < 4; c4++) acc += dot4(w4[c4], &s_h1[0][c4 * 4]);
            s_h2[0][lane] = relu(acc);
        }
        __syncwarp();
        if (lane < 8) {
            const float4* w4 = reinterpret_cast<const float4*>(&w.q_w3[lane * 16]);
            float acc = w.q_b3[lane];
            #pragma unroll
            for (int c4 = 0; c4 < 4; c4++) acc += dot4(w4[c4], &s_h2[0][c4 * 4]);
            s_q[0][lane] = relu(acc);
        }
        __syncwarp();
        if (lane < 2) {
            out[n4 - 2 + lane] = (lane == 0)
                ? *reinterpret_cast<const float4*>(&s_q[0][0])
                : *reinterpret_cast<const float4*>(&s_q[0][4]);
        }
    }

    // ==== Fill: light blocks split [0, n4-2) ====
    if (!heavy) {
        __syncthreads();   // q_common visible
        const float4 qc0 = *reinterpret_cast<const float4*>(&s_q[1][0]);
        const float4 qc1 = *reinterpret_cast<const float4*>(&s_q[1][4]);
        const int stride = (gridDim.x - 1) * NT;
        for (int i = (blockIdx.x - 1) * NT + t; i < n4 - 2; i += stride)
            out[i] = (i & 1) ? qc1 : qc0;
    }
}

extern "C" void kernel_launch(void* const* d_in, const int* in_sizes, int n_in,
                              void* d_out, int out_size) {
    const float* state = (const float*)d_in[0];
    const int B = in_sizes[0] / 16;

    const float* dv_w1 = (const float*)d_in[1];
    const float* dv_b1 = (const float*)d_in[2];
    const float* dv_w2 = (const float*)d_in[3];
    const float* dv_b2 = (const float*)d_in[4];
    const float* dp_w1 = (const float*)d_in[5];
    const float* dp_b1 = (const float*)d_in[6];
    const float* dp_w2 = (const float*)d_in[7];
    const float* dp_b2 = (const float*)d_in[8];
    const float* emb_w = (const float*)d_in[9];
    const float* emb_b = (const float*)d_in[10];
    const float* cp_w1 = (const float*)d_in[11];
    const float* cp_b1 = (const float*)d_in[12];
    const float* cp_w2 = (const float*)d_in[13];
    const float* cp_b2 = (const float*)d_in[14];
    const float* cm_w1 = (const float*)d_in[15];
    const float* cm_b1 = (const float*)d_in[16];
    const float* cm_w2 = (const float*)d_in[17];
    const float* cm_b2 = (const float*)d_in[18];
    const float* cm_w3 = (const float*)d_in[19];
    const float* cm_b3 = (const float*)d_in[20];
    const float* cc_w1 = (const float*)d_in[21];
    const float* cc_b1 = (const float*)d_in[22];
    const float* cc_w2 = (const float*)d_in[23];
    const float* cc_b2 = (const float*)d_in[24];
    const float* q_w1  = (const float*)d_in[25];
    const float* q_b1  = (const float*)d_in[26];
    const float* q_w2  = (const float*)d_in[27];
    const float* q_b2  = (const float*)d_in[28];
    const float* q_w3  = (const float*)d_in[29];
    const float* q_b3  = (const float*)d_in[30];
    const float* mask  = (const float*)d_in[31];

    const int n4 = out_size / 4;
    frap_fused_kernel<<<148, NT>>>(
        state, B,
        dv_w1, dv_b1, dv_w2, dv_b2,
        dp_w1, dp_b1, dp_w2, dp_b2,
        emb_w, emb_b,
        cp_w1, cp_b1, cp_w2, cp_b2,
        cm_w1, cm_b1, cm_w2, cm_b2, cm_w3, cm_b3,
        cc_w1, cc_b1, cc_w2, cc_b2,
        q_w1, q_b1, q_w2, q_b2, q_w3, q_b3,
        mask,
        (float4*)d_out, n4);
}